// round 1
// baseline (speedup 1.0000x reference)
#include <cuda_runtime.h>
#include <math.h>

// Problem constants (fixed shapes per reference: B=4096, D=256, T=0.5)
#define NB     4096
#define D      256
#define N2     8192          // 2B rows
#define TINV   2.0f          // 1/T
#define NS     4             // j-splits per row-tile
#define JSPAN  (N2 / NS)     // 2048 cols per block
#define BM     128
#define BN     128
#define BK     32
#define SPAD   4

// Scratch (static device globals; no allocation allowed)
__device__ float g_z[N2 * D];          // normalized rows [8192][256]
__device__ float g_partial[N2 * NS];   // per-row partial exp-sums per split
__device__ float g_pos[N2];            // sim[k, (k+-B)]

// ---------------------------------------------------------------------------
// Kernel 1: L2-normalize rows of x_i / x_j into g_z.  1 warp per row.
// ---------------------------------------------------------------------------
__global__ __launch_bounds__(256) void knorm(const float* __restrict__ xi,
                                             const float* __restrict__ xj) {
    int warp = threadIdx.x >> 5;
    int lane = threadIdx.x & 31;
    int row  = blockIdx.x * 8 + warp;           // grid = N2/8 blocks
    const float* src = (row < NB) ? (xi + (size_t)row * D)
                                  : (xj + (size_t)(row - NB) * D);
    float4 v0 = ((const float4*)src)[lane];
    float4 v1 = ((const float4*)src)[lane + 32];
    float ss = v0.x*v0.x + v0.y*v0.y + v0.z*v0.z + v0.w*v0.w
             + v1.x*v1.x + v1.y*v1.y + v1.z*v1.z + v1.w*v1.w;
#pragma unroll
    for (int off = 16; off > 0; off >>= 1)
        ss += __shfl_xor_sync(0xffffffffu, ss, off);
    float scale = 1.0f / fmaxf(sqrtf(ss), 1e-12f);   // matches F.normalize eps
    float4 o0 = make_float4(v0.x*scale, v0.y*scale, v0.z*scale, v0.w*scale);
    float4 o1 = make_float4(v1.x*scale, v1.y*scale, v1.z*scale, v1.w*scale);
    float* dst = g_z + (size_t)row * D;
    ((float4*)dst)[lane]      = o0;
    ((float4*)dst)[lane + 32] = o1;
}

// ---------------------------------------------------------------------------
// Kernel 2: fused sim-GEMM + exp-sum epilogue.
// Block: 256 threads, output tile BM x BN, 8x8 per thread.
// grid = (N2/BM row-tiles, NS j-splits). Each block scans JSPAN columns.
// ---------------------------------------------------------------------------
__global__ __launch_bounds__(256, 2) void kmain() {
    const int rowbase = blockIdx.x * BM;
    const int split   = blockIdx.y;
    const int jbase0  = split * JSPAN;

    __shared__ float As[BK][BM + SPAD];
    __shared__ float Bs[BK][BN + SPAD];
    __shared__ float red[BM][17];

    const int tid = threadIdx.x;
    const int tx  = tid & 15;        // 0..15 -> col group
    const int ty  = tid >> 4;        // 0..15 -> row group
    const int ldr = tid >> 3;        // 0..31  row within load pass
    const int lds = tid & 7;         // 0..7   16B segment within 128B k-window

    float rowsum[8];
#pragma unroll
    for (int i = 0; i < 8; i++) rowsum[i] = 0.0f;

    for (int jt = 0; jt < JSPAN; jt += BN) {
        const int jbase = jbase0 + jt;
        float acc[8][8];
#pragma unroll
        for (int i = 0; i < 8; i++)
#pragma unroll
            for (int j = 0; j < 8; j++) acc[i][j] = 0.0f;

        for (int k0 = 0; k0 < D; k0 += BK) {
            // Load A(128x32) and B(128x32) tiles, transposed into [k][m] smem.
#pragma unroll
            for (int it = 0; it < 4; it++) {
                int r = ldr + it * 32;
                float4 va = *(const float4*)&g_z[(size_t)(rowbase + r) * D + k0 + lds * 4];
                As[lds*4 + 0][r] = va.x;
                As[lds*4 + 1][r] = va.y;
                As[lds*4 + 2][r] = va.z;
                As[lds*4 + 3][r] = va.w;
                float4 vb = *(const float4*)&g_z[(size_t)(jbase + r) * D + k0 + lds * 4];
                Bs[lds*4 + 0][r] = vb.x;
                Bs[lds*4 + 1][r] = vb.y;
                Bs[lds*4 + 2][r] = vb.z;
                Bs[lds*4 + 3][r] = vb.w;
            }
            __syncthreads();
#pragma unroll
            for (int kk = 0; kk < BK; kk++) {
                float a[8], b[8];
                *(float4*)&a[0] = *(const float4*)&As[kk][ty * 8];
                *(float4*)&a[4] = *(const float4*)&As[kk][ty * 8 + 4];
                *(float4*)&b[0] = *(const float4*)&Bs[kk][tx * 8];
                *(float4*)&b[4] = *(const float4*)&Bs[kk][tx * 8 + 4];
#pragma unroll
                for (int i = 0; i < 8; i++)
#pragma unroll
                    for (int j = 0; j < 8; j++)
                        acc[i][j] = fmaf(a[i], b[j], acc[i][j]);
            }
            __syncthreads();
        }

        // Epilogue: exp-sum with diagonal exclusion + pos capture.
#pragma unroll
        for (int i = 0; i < 8; i++) {
            const int gm = rowbase + ty * 8 + i;
#pragma unroll
            for (int j = 0; j < 8; j++) {
                const int gn = jbase + tx * 8 + j;
                const float s = acc[i][j];
                if (gn == gm + NB || gn == gm - NB) g_pos[gm] = s;
                if (gn != gm) rowsum[i] += __expf(s * TINV);
            }
        }
    }

    // Reduce rowsum across the 16 col-group threads of each row.
#pragma unroll
    for (int i = 0; i < 8; i++) red[ty * 8 + i][tx] = rowsum[i];
    __syncthreads();
    if (tid < BM) {
        float s = 0.0f;
#pragma unroll
        for (int t = 0; t < 16; t++) s += red[tid][t];
        g_partial[(size_t)(rowbase + tid) * NS + split] = s;
    }
}

// ---------------------------------------------------------------------------
// Kernel 3: combine partials -> per-row loss -> deterministic scalar reduce.
// ---------------------------------------------------------------------------
__global__ __launch_bounds__(256) void kfinal(float* __restrict__ out) {
    __shared__ float red[256];
    const int tid = threadIdx.x;
    float s = 0.0f;
    for (int r = tid; r < N2; r += 256) {
        float denom = 0.0f;
#pragma unroll
        for (int t = 0; t < NS; t++) denom += g_partial[(size_t)r * NS + t];
        s += -g_pos[r] * TINV + logf(denom);
    }
    red[tid] = s;
    __syncthreads();
    for (int off = 128; off > 0; off >>= 1) {
        if (tid < off) red[tid] += red[tid + off];
        __syncthreads();
    }
    if (tid == 0) out[0] = red[0] / (float)N2;
}

// ---------------------------------------------------------------------------
extern "C" void kernel_launch(void* const* d_in, const int* in_sizes, int n_in,
                              void* d_out, int out_size) {
    const float* xi = (const float*)d_in[0];
    const float* xj = (const float*)d_in[1];
    float* out = (float*)d_out;
    (void)in_sizes; (void)n_in; (void)out_size;

    knorm<<<N2 / 8, 256>>>(xi, xj);
    kmain<<<dim3(N2 / BM, NS), 256>>>();
    kfinal<<<1, 256>>>(out);
}

// round 3
// speedup vs baseline: 2.5455x; 2.5455x over previous
#include <cuda_runtime.h>
#include <cuda_fp16.h>
#include <math.h>
#include <stdint.h>

// Problem constants (fixed shapes: B=4096, D=256, T=0.5)
#define NB     4096
#define D      256
#define N2     8192
#define BM     128
#define BN     128
#define BK     32
#define NKC    (D / BK)      // 8 k-chunks
#define NCT    (N2 / BN)     // 64 col tiles
#define NRT    (N2 / BM)     // 64 row tiles
#define PITCH  80            // smem row pitch bytes (64B data + 16B pad)
#define STAGE_BYTES (2 * BM * PITCH)   // A + B tile = 20480
#define NSTAGE 4
#define RED_OFF (NSTAGE * STAGE_BYTES) // 81920
#define SMEM_BYTES (RED_OFF + BM * 4 * 4)  // + red[128][4]

// Scratch (static device globals; no allocation allowed)
__device__ __half g_zh[N2 * D];        // normalized rows, fp16
__device__ float g_partial[N2 * NCT];  // per-row exp-sum partial per col tile
__device__ float g_pos[N2];            // sim[k, k +- NB]

// ---------------------------------------------------------------------------
__device__ __forceinline__ uint32_t smem_u32(const void* p) {
    uint32_t a;
    asm("{ .reg .u64 t; cvta.to.shared.u64 t, %1; cvt.u32.u64 %0, t; }"
        : "=r"(a) : "l"(p));
    return a;
}
__device__ __forceinline__ void cp_async16(uint32_t smem, const void* g) {
    asm volatile("cp.async.cg.shared.global [%0], [%1], 16;" :: "r"(smem), "l"(g));
}
#define CP_COMMIT() asm volatile("cp.async.commit_group;" ::: "memory")
#define CP_WAIT(n)  asm volatile("cp.async.wait_group %0;" :: "n"(n) : "memory")

__device__ __forceinline__ void ldsm4(uint32_t* r, uint32_t addr) {
    asm volatile("ldmatrix.sync.aligned.m8n8.x4.shared.b16 {%0,%1,%2,%3}, [%4];"
        : "=r"(r[0]), "=r"(r[1]), "=r"(r[2]), "=r"(r[3]) : "r"(addr));
}
__device__ __forceinline__ void ldsm2(uint32_t* r, uint32_t addr) {
    asm volatile("ldmatrix.sync.aligned.m8n8.x2.shared.b16 {%0,%1}, [%2];"
        : "=r"(r[0]), "=r"(r[1]) : "r"(addr));
}
__device__ __forceinline__ void mma16816(float* c, const uint32_t* a, const uint32_t* b) {
    asm volatile("mma.sync.aligned.m16n8k16.row.col.f32.f16.f16.f32 "
        "{%0,%1,%2,%3}, {%4,%5,%6,%7}, {%8,%9}, {%0,%1,%2,%3};"
        : "+f"(c[0]), "+f"(c[1]), "+f"(c[2]), "+f"(c[3])
        : "r"(a[0]), "r"(a[1]), "r"(a[2]), "r"(a[3]), "r"(b[0]), "r"(b[1]));
}

// ---------------------------------------------------------------------------
// Kernel 1: L2-normalize rows of x_i / x_j (fp32 math) into fp16 g_zh.
// ---------------------------------------------------------------------------
__global__ __launch_bounds__(256) void knorm(const float* __restrict__ xi,
                                             const float* __restrict__ xj) {
    int warp = threadIdx.x >> 5;
    int lane = threadIdx.x & 31;
    int row  = blockIdx.x * 8 + warp;
    const float* src = (row < NB) ? (xi + (size_t)row * D)
                                  : (xj + (size_t)(row - NB) * D);
    float4 v0 = ((const float4*)src)[lane];
    float4 v1 = ((const float4*)src)[lane + 32];
    float ss = v0.x*v0.x + v0.y*v0.y + v0.z*v0.z + v0.w*v0.w
             + v1.x*v1.x + v1.y*v1.y + v1.z*v1.z + v1.w*v1.w;
#pragma unroll
    for (int off = 16; off > 0; off >>= 1)
        ss += __shfl_xor_sync(0xffffffffu, ss, off);
    float sc = 1.0f / fmaxf(sqrtf(ss), 1e-12f);
    __half2* dst = (__half2*)(g_zh + (size_t)row * D);
    dst[lane * 2 + 0]  = __floats2half2_rn(v0.x * sc, v0.y * sc);
    dst[lane * 2 + 1]  = __floats2half2_rn(v0.z * sc, v0.w * sc);
    dst[64 + lane * 2] = __floats2half2_rn(v1.x * sc, v1.y * sc);
    dst[65 + lane * 2] = __floats2half2_rn(v1.z * sc, v1.w * sc);
}

// ---------------------------------------------------------------------------
// Stage loader: A(128x32) + B(128x32) fp16 tiles via cp.async.
// ---------------------------------------------------------------------------
__device__ __forceinline__ void load_stage(uint32_t sbase, int rb, int cb,
                                           int k0, int tid) {
    const uint32_t aB = sbase, bB = sbase + BM * PITCH;
#pragma unroll
    for (int i = 0; i < 2; i++) {
        int t = tid + i * 256;
        int row = t >> 2, seg = t & 3;
        uint32_t so = (uint32_t)(row * PITCH + seg * 16);
        cp_async16(aB + so, g_zh + (size_t)(rb + row) * D + k0 + seg * 8);
        cp_async16(bB + so, g_zh + (size_t)(cb + row) * D + k0 + seg * 8);
    }
}

// ---------------------------------------------------------------------------
// Kernel 2: fp16 tensor-core sim-GEMM (128x128 tile) + fused exp-sum.
// 8 warps (2 m x 4 n), warp tile 64x32, m16n8k16 fragments.
// ---------------------------------------------------------------------------
__global__ __launch_bounds__(256, 2) void kmain_hmma() {
    extern __shared__ char smem[];
    const uint32_t sb = smem_u32(smem);
    float* red = (float*)(smem + RED_OFF);    // [128][4]

    const int tid = threadIdx.x;
    const int wid = tid >> 5, lid = tid & 31;
    const int wm = wid >> 2;                  // 0..1  (rows wm*64)
    const int wn = wid & 3;                   // 0..3  (cols wn*32)
    const int rb = blockIdx.x * BM;
    const int cb = blockIdx.y * BN;

    float acc[4][4][4];
#pragma unroll
    for (int i = 0; i < 4; i++)
#pragma unroll
        for (int j = 0; j < 4; j++)
#pragma unroll
            for (int e = 0; e < 4; e++) acc[i][j][e] = 0.0f;

    // Prologue: fill 3 of 4 stages
    load_stage(sb + 0 * STAGE_BYTES, rb, cb, 0 * BK, tid); CP_COMMIT();
    load_stage(sb + 1 * STAGE_BYTES, rb, cb, 1 * BK, tid); CP_COMMIT();
    load_stage(sb + 2 * STAGE_BYTES, rb, cb, 2 * BK, tid); CP_COMMIT();

    const int arow  = (lid & 7) + ((lid >> 3) & 1) * 8;
    const int akoff = (lid >> 4) * 16;
    const int brow  = lid & 7;
    const int bkoff = ((lid >> 3) & 1) * 16;

#pragma unroll
    for (int k = 0; k < NKC; k++) {
        if (k <= 5)      { CP_WAIT(2); }
        else if (k == 6) { CP_WAIT(1); }
        else             { CP_WAIT(0); }
        __syncthreads();
        if (k + 3 < NKC) {
            load_stage(sb + ((k + 3) & 3) * STAGE_BYTES, rb, cb, (k + 3) * BK, tid);
            CP_COMMIT();
        }
        const uint32_t aB = sb + (k & 3) * STAGE_BYTES;
        const uint32_t bB = aB + BM * PITCH;
#pragma unroll
        for (int kf = 0; kf < 2; kf++) {
            uint32_t af[4][4], bf[4][2];
#pragma unroll
            for (int i = 0; i < 4; i++)
                ldsm4(af[i], aB + (uint32_t)((wm * 64 + i * 16 + arow) * PITCH
                                             + kf * 32 + akoff));
#pragma unroll
            for (int j = 0; j < 4; j++)
                ldsm2(bf[j], bB + (uint32_t)((wn * 32 + j * 8 + brow) * PITCH
                                             + kf * 32 + bkoff));
#pragma unroll
            for (int i = 0; i < 4; i++)
#pragma unroll
                for (int j = 0; j < 4; j++)
                    mma16816(acc[i][j], af[i], bf[j]);
        }
    }

    // Epilogue on register fragments.
    // acc elem (i,j,e): row = wm*64 + i*16 + (lid>>2) + (e>=2)*8
    //                   col = wn*32 + j*8  + (lid&3)*2 + (e&1)
    const int r0 = lid >> 2;
    const int c0 = (lid & 3) * 2;
    float rsum[4][2];
#pragma unroll
    for (int i = 0; i < 4; i++) { rsum[i][0] = 0.0f; rsum[i][1] = 0.0f; }

#pragma unroll
    for (int i = 0; i < 4; i++)
#pragma unroll
        for (int j = 0; j < 4; j++)
#pragma unroll
            for (int e = 0; e < 4; e++) {
                const int h  = e >> 1;
                const int gm = rb + wm * 64 + i * 16 + r0 + h * 8;
                const int gn = cb + wn * 32 + j * 8 + c0 + (e & 1);
                const float v = acc[i][j][e];
                if (gn == gm + NB || gn == gm - NB) g_pos[gm] = v;
                if (gn != gm) rsum[i][h] += __expf(v * 2.0f);
            }

    // Reduce over the 4 lanes sharing a row (lid&3), then across 4 n-warps.
#pragma unroll
    for (int i = 0; i < 4; i++)
#pragma unroll
        for (int h = 0; h < 2; h++) {
#pragma unroll
            for (int off = 1; off <= 2; off <<= 1)
                rsum[i][h] += __shfl_xor_sync(0xffffffffu, rsum[i][h], off);
        }
    if ((lid & 3) == 0) {
#pragma unroll
        for (int i = 0; i < 4; i++)
#pragma unroll
            for (int h = 0; h < 2; h++)
                red[(wm * 64 + i * 16 + r0 + h * 8) * 4 + wn] = rsum[i][h];
    }
    __syncthreads();
    if (tid < BM) {
        g_partial[(size_t)(rb + tid) * NCT + blockIdx.y] =
            red[tid * 4] + red[tid * 4 + 1] + red[tid * 4 + 2] + red[tid * 4 + 3];
    }
}

// ---------------------------------------------------------------------------
// Kernel 3: combine partials -> per-row loss -> deterministic scalar reduce.
// ---------------------------------------------------------------------------
__global__ __launch_bounds__(256) void kfinal(float* __restrict__ out) {
    __shared__ float red[256];
    const int tid = threadIdx.x;
    float s = 0.0f;
    for (int r = tid; r < N2; r += 256) {
        float denom = 0.0f;
#pragma unroll
        for (int t = 0; t < NCT; t++) denom += g_partial[(size_t)r * NCT + t];
        s += -g_pos[r] * 2.0f + logf(denom);
    }
    red[tid] = s;
    __syncthreads();
    for (int off = 128; off > 0; off >>= 1) {
        if (tid < off) red[tid] += red[tid + off];
        __syncthreads();
    }
    if (tid == 0) out[0] = red[0] / (float)N2;
}

// ---------------------------------------------------------------------------
extern "C" void kernel_launch(void* const* d_in, const int* in_sizes, int n_in,
                              void* d_out, int out_size) {
    const float* xi = (const float*)d_in[0];
    const float* xj = (const float*)d_in[1];
    float* out = (float*)d_out;
    (void)in_sizes; (void)n_in; (void)out_size;

    cudaFuncSetAttribute(kmain_hmma,
                         cudaFuncAttributeMaxDynamicSharedMemorySize, SMEM_BYTES);

    knorm<<<N2 / 8, 256>>>(xi, xj);
    kmain_hmma<<<dim3(NRT, NCT), 256, SMEM_BYTES>>>();
    kfinal<<<1, 256>>>(out);
}

// round 4
// speedup vs baseline: 2.8908x; 1.1356x over previous
#include <cuda_runtime.h>
#include <cuda_fp16.h>
#include <math.h>
#include <stdint.h>

// Problem constants (fixed shapes: B=4096, D=256, T=0.5)
#define NB     4096
#define D      256
#define N2     8192
#define BM     128
#define BN     128
#define BK     32
#define NKC    (D / BK)      // 8 k-chunks
#define NCT    (N2 / BN)     // 64 col tiles
#define NRT    (N2 / BM)     // 64 row tiles
#define NTRI   (NRT * (NRT + 1) / 2)   // 2080 upper-tri tiles
#define PITCH  80            // smem row pitch bytes (64B data + 16B pad)
#define STAGE_BYTES (2 * BM * PITCH)   // A + B tile = 20480
#define NSTAGE 4
#define REDR_OFF (NSTAGE * STAGE_BYTES)          // 81920: red_row[128][4]
#define REDC_OFF (REDR_OFF + BM * 4 * 4)         // red_col[128][2]
#define SMEM_BYTES (REDC_OFF + BM * 2 * 4)

// Scratch (static device globals; no allocation allowed)
__device__ __half g_zh[N2 * D];        // normalized rows, fp16
__device__ float g_partial[N2 * NCT];  // per-row exp-sum partial per slot
__device__ float g_pos[N2];            // sim[k, k +- NB]

// ---------------------------------------------------------------------------
__device__ __forceinline__ uint32_t smem_u32(const void* p) {
    uint32_t a;
    asm("{ .reg .u64 t; cvta.to.shared.u64 t, %1; cvt.u32.u64 %0, t; }"
        : "=r"(a) : "l"(p));
    return a;
}
__device__ __forceinline__ void cp_async16(uint32_t smem, const void* g) {
    asm volatile("cp.async.cg.shared.global [%0], [%1], 16;" :: "r"(smem), "l"(g));
}
#define CP_COMMIT() asm volatile("cp.async.commit_group;" ::: "memory")
#define CP_WAIT(n)  asm volatile("cp.async.wait_group %0;" :: "n"(n) : "memory")

__device__ __forceinline__ void ldsm4(uint32_t* r, uint32_t addr) {
    asm volatile("ldmatrix.sync.aligned.m8n8.x4.shared.b16 {%0,%1,%2,%3}, [%4];"
        : "=r"(r[0]), "=r"(r[1]), "=r"(r[2]), "=r"(r[3]) : "r"(addr));
}
__device__ __forceinline__ void ldsm2(uint32_t* r, uint32_t addr) {
    asm volatile("ldmatrix.sync.aligned.m8n8.x2.shared.b16 {%0,%1}, [%2];"
        : "=r"(r[0]), "=r"(r[1]) : "r"(addr));
}
__device__ __forceinline__ void mma16816(float* c, const uint32_t* a, const uint32_t* b) {
    asm volatile("mma.sync.aligned.m16n8k16.row.col.f32.f16.f16.f32 "
        "{%0,%1,%2,%3}, {%4,%5,%6,%7}, {%8,%9}, {%0,%1,%2,%3};"
        : "+f"(c[0]), "+f"(c[1]), "+f"(c[2]), "+f"(c[3])
        : "r"(a[0]), "r"(a[1]), "r"(a[2]), "r"(a[3]), "r"(b[0]), "r"(b[1]));
}

// ---------------------------------------------------------------------------
// Kernel 1: L2-normalize rows of x_i / x_j (fp32 math) into fp16 g_zh.
// ---------------------------------------------------------------------------
__global__ __launch_bounds__(256) void knorm(const float* __restrict__ xi,
                                             const float* __restrict__ xj) {
    int warp = threadIdx.x >> 5;
    int lane = threadIdx.x & 31;
    int row  = blockIdx.x * 8 + warp;
    const float* src = (row < NB) ? (xi + (size_t)row * D)
                                  : (xj + (size_t)(row - NB) * D);
    float4 v0 = ((const float4*)src)[lane];
    float4 v1 = ((const float4*)src)[lane + 32];
    float ss = v0.x*v0.x + v0.y*v0.y + v0.z*v0.z + v0.w*v0.w
             + v1.x*v1.x + v1.y*v1.y + v1.z*v1.z + v1.w*v1.w;
#pragma unroll
    for (int off = 16; off > 0; off >>= 1)
        ss += __shfl_xor_sync(0xffffffffu, ss, off);
    float sc = 1.0f / fmaxf(sqrtf(ss), 1e-12f);
    __half2* dst = (__half2*)(g_zh + (size_t)row * D);
    dst[lane * 2 + 0]  = __floats2half2_rn(v0.x * sc, v0.y * sc);
    dst[lane * 2 + 1]  = __floats2half2_rn(v0.z * sc, v0.w * sc);
    dst[64 + lane * 2] = __floats2half2_rn(v1.x * sc, v1.y * sc);
    dst[65 + lane * 2] = __floats2half2_rn(v1.z * sc, v1.w * sc);
}

// ---------------------------------------------------------------------------
// Stage loader: A(128x32) + B(128x32) fp16 tiles via cp.async.
// ---------------------------------------------------------------------------
__device__ __forceinline__ void load_stage(uint32_t sbase, int rb, int cb,
                                           int k0, int tid) {
    const uint32_t aB = sbase, bB = sbase + BM * PITCH;
#pragma unroll
    for (int i = 0; i < 2; i++) {
        int t = tid + i * 256;
        int row = t >> 2, seg = t & 3;
        uint32_t so = (uint32_t)(row * PITCH + seg * 16);
        cp_async16(aB + so, g_zh + (size_t)(rb + row) * D + k0 + seg * 8);
        cp_async16(bB + so, g_zh + (size_t)(cb + row) * D + k0 + seg * 8);
    }
}

// ---------------------------------------------------------------------------
// Kernel 2: fp16 HMMA sim-GEMM on UPPER-TRIANGULAR tiles only (symmetry).
// Off-diagonal tile (it<jt): exp values feed denom of both rows AND cols.
// 8 warps (2 m x 4 n), warp tile 64x32, m16n8k16 fragments.
// ---------------------------------------------------------------------------
__global__ __launch_bounds__(256, 2) void kmain_hmma() {
    extern __shared__ char smem[];
    const uint32_t sb = smem_u32(smem);
    float* red_row = (float*)(smem + REDR_OFF);   // [128][4]
    float* red_col = (float*)(smem + REDC_OFF);   // [128][2]

    // Triangular decode: linear blockIdx -> (it, jt), it <= jt.
    int rem = blockIdx.x;
    int it = 0;
    while (rem >= NRT - it) { rem -= NRT - it; it++; }
    const int jt = it + rem;
    const bool offd = (jt > it);

    const int tid = threadIdx.x;
    const int wid = tid >> 5, lid = tid & 31;
    const int wm = wid >> 2;                  // 0..1  (rows wm*64)
    const int wn = wid & 3;                   // 0..3  (cols wn*32)
    const int rb = it * BM;
    const int cb = jt * BN;

    float acc[4][4][4];
#pragma unroll
    for (int i = 0; i < 4; i++)
#pragma unroll
        for (int j = 0; j < 4; j++)
#pragma unroll
            for (int e = 0; e < 4; e++) acc[i][j][e] = 0.0f;

    // Prologue: fill 3 of 4 stages
    load_stage(sb + 0 * STAGE_BYTES, rb, cb, 0 * BK, tid); CP_COMMIT();
    load_stage(sb + 1 * STAGE_BYTES, rb, cb, 1 * BK, tid); CP_COMMIT();
    load_stage(sb + 2 * STAGE_BYTES, rb, cb, 2 * BK, tid); CP_COMMIT();

    const int arow  = (lid & 7) + ((lid >> 3) & 1) * 8;
    const int akoff = (lid >> 4) * 16;
    const int brow  = lid & 7;
    const int bkoff = ((lid >> 3) & 1) * 16;

#pragma unroll
    for (int k = 0; k < NKC; k++) {
        if (k <= 5)      { CP_WAIT(2); }
        else if (k == 6) { CP_WAIT(1); }
        else             { CP_WAIT(0); }
        __syncthreads();
        if (k + 3 < NKC) {
            load_stage(sb + ((k + 3) & 3) * STAGE_BYTES, rb, cb, (k + 3) * BK, tid);
            CP_COMMIT();
        }
        const uint32_t aB = sb + (k & 3) * STAGE_BYTES;
        const uint32_t bB = aB + BM * PITCH;
#pragma unroll
        for (int kf = 0; kf < 2; kf++) {
            uint32_t af[4][4], bf[4][2];
#pragma unroll
            for (int i = 0; i < 4; i++)
                ldsm4(af[i], aB + (uint32_t)((wm * 64 + i * 16 + arow) * PITCH
                                             + kf * 32 + akoff));
#pragma unroll
            for (int j = 0; j < 4; j++)
                ldsm2(bf[j], bB + (uint32_t)((wn * 32 + j * 8 + brow) * PITCH
                                             + kf * 32 + bkoff));
#pragma unroll
            for (int i = 0; i < 4; i++)
#pragma unroll
                for (int j = 0; j < 4; j++)
                    mma16816(acc[i][j], af[i], bf[j]);
        }
    }

    // Epilogue on register fragments.
    // acc elem (i,j,e): row = wm*64 + i*16 + (lid>>2) + (e>=2)*8
    //                   col = wn*32 + j*8  + (lid&3)*2 + (e&1)
    const int r0 = lid >> 2;
    const int c0 = (lid & 3) * 2;
    float rsum[4][2], csum[4][2];
#pragma unroll
    for (int i = 0; i < 4; i++) {
        rsum[i][0] = 0.0f; rsum[i][1] = 0.0f;
        csum[i][0] = 0.0f; csum[i][1] = 0.0f;
    }

#pragma unroll
    for (int i = 0; i < 4; i++)
#pragma unroll
        for (int j = 0; j < 4; j++)
#pragma unroll
            for (int e = 0; e < 4; e++) {
                const int h  = e >> 1, ec = e & 1;
                const int gm = rb + wm * 64 + i * 16 + r0 + h * 8;
                const int gn = cb + wn * 32 + j * 8 + c0 + ec;
                const float v = acc[i][j][e];
                if (gn == gm + NB) { g_pos[gm] = v; g_pos[gn] = v; }
                const float ev = __expf(v * 2.0f);
                if (offd) {
                    rsum[i][h]  += ev;
                    csum[j][ec] += ev;
                } else if (gn != gm) {
                    rsum[i][h]  += ev;
                }
            }

    // Row reduce: over the 4 lanes sharing a row (lid&3), then 4 n-warps.
#pragma unroll
    for (int i = 0; i < 4; i++)
#pragma unroll
        for (int h = 0; h < 2; h++) {
#pragma unroll
            for (int off = 1; off <= 2; off <<= 1)
                rsum[i][h] += __shfl_xor_sync(0xffffffffu, rsum[i][h], off);
        }
    if ((lid & 3) == 0) {
#pragma unroll
        for (int i = 0; i < 4; i++)
#pragma unroll
            for (int h = 0; h < 2; h++)
                red_row[(wm * 64 + i * 16 + r0 + h * 8) * 4 + wn] = rsum[i][h];
    }

    // Col reduce (off-diag only): over the 8 lane row-groups (xor 4,8,16),
    // then the 2 m-warps via smem.
    if (offd) {
#pragma unroll
        for (int j = 0; j < 4; j++)
#pragma unroll
            for (int ec = 0; ec < 2; ec++) {
#pragma unroll
                for (int off = 4; off <= 16; off <<= 1)
                    csum[j][ec] += __shfl_xor_sync(0xffffffffu, csum[j][ec], off);
            }
        if (lid < 4) {
#pragma unroll
            for (int j = 0; j < 4; j++)
#pragma unroll
                for (int ec = 0; ec < 2; ec++)
                    red_col[(wn * 32 + j * 8 + lid * 2 + ec) * 2 + wm] = csum[j][ec];
        }
    }
    __syncthreads();
    if (tid < BM) {
        g_partial[(size_t)(rb + tid) * NCT + jt] =
            red_row[tid * 4] + red_row[tid * 4 + 1]
          + red_row[tid * 4 + 2] + red_row[tid * 4 + 3];
        if (offd)
            g_partial[(size_t)(cb + tid) * NCT + it] =
                red_col[tid * 2] + red_col[tid * 2 + 1];
    }
}

// ---------------------------------------------------------------------------
// Kernel 3: combine partials -> per-row loss -> deterministic scalar reduce.
// ---------------------------------------------------------------------------
__global__ __launch_bounds__(256) void kfinal(float* __restrict__ out) {
    __shared__ float red[256];
    const int tid = threadIdx.x;
    float s = 0.0f;
    for (int r = tid; r < N2; r += 256) {
        float denom = 0.0f;
#pragma unroll
        for (int t = 0; t < NCT; t++) denom += g_partial[(size_t)r * NCT + t];
        s += -g_pos[r] * 2.0f + logf(denom);
    }
    red[tid] = s;
    __syncthreads();
    for (int off = 128; off > 0; off >>= 1) {
        if (tid < off) red[tid] += red[tid + off];
        __syncthreads();
    }
    if (tid == 0) out[0] = red[0] / (float)N2;
}

// ---------------------------------------------------------------------------
extern "C" void kernel_launch(void* const* d_in, const int* in_sizes, int n_in,
                              void* d_out, int out_size) {
    const float* xi = (const float*)d_in[0];
    const float* xj = (const float*)d_in[1];
    float* out = (float*)d_out;
    (void)in_sizes; (void)n_in; (void)out_size;

    cudaFuncSetAttribute(kmain_hmma,
                         cudaFuncAttributeMaxDynamicSharedMemorySize, SMEM_BYTES);

    knorm<<<N2 / 8, 256>>>(xi, xj);
    kmain_hmma<<<NTRI, 256, SMEM_BYTES>>>();
    kfinal<<<1, 256>>>(out);
}

// round 5
// speedup vs baseline: 2.9115x; 1.0072x over previous
#include <cuda_runtime.h>
#include <cuda_fp16.h>
#include <math.h>
#include <stdint.h>

// Problem constants (fixed shapes: B=4096, D=256, T=0.5)
#define NB     4096
#define D      256
#define N2     8192
#define BM     128
#define BN     128
#define BK     32
#define NKC    (D / BK)      // 8 k-chunks
#define NCT    (N2 / BN)     // 64 col tiles
#define NRT    (N2 / BM)     // 64 row tiles
#define NTRI   (NRT * (NRT + 1) / 2)   // 2080 upper-tri tiles
#define PITCH  80            // smem row pitch bytes (64B data + 16B pad)
#define STAGE_BYTES (2 * BM * PITCH)   // A + B tile = 20480
#define NSTAGE 4
#define REDR_OFF (NSTAGE * STAGE_BYTES)          // 81920: red_row[128][4]
#define REDC_OFF (REDR_OFF + BM * 4 * 4)         // red_col[128][2]
#define SMEM_BYTES (REDC_OFF + BM * 2 * 4)

// Scratch (static device globals; no allocation allowed)
__device__ __half g_zh[N2 * D];        // normalized rows, fp16
__device__ float g_partial[N2 * NCT];  // per-row exp-sum partial per slot
__device__ float g_pos[N2];            // sim[k, k +- NB]

// ---------------------------------------------------------------------------
__device__ __forceinline__ uint32_t smem_u32(const void* p) {
    uint32_t a;
    asm("{ .reg .u64 t; cvta.to.shared.u64 t, %1; cvt.u32.u64 %0, t; }"
        : "=r"(a) : "l"(p));
    return a;
}
__device__ __forceinline__ void cp_async16(uint32_t smem, const void* g) {
    asm volatile("cp.async.cg.shared.global [%0], [%1], 16;" :: "r"(smem), "l"(g));
}
#define CP_COMMIT() asm volatile("cp.async.commit_group;" ::: "memory")
#define CP_WAIT(n)  asm volatile("cp.async.wait_group %0;" :: "n"(n) : "memory")

__device__ __forceinline__ void ldsm4(uint32_t* r, uint32_t addr) {
    asm volatile("ldmatrix.sync.aligned.m8n8.x4.shared.b16 {%0,%1,%2,%3}, [%4];"
        : "=r"(r[0]), "=r"(r[1]), "=r"(r[2]), "=r"(r[3]) : "r"(addr));
}
__device__ __forceinline__ void ldsm2(uint32_t* r, uint32_t addr) {
    asm volatile("ldmatrix.sync.aligned.m8n8.x2.shared.b16 {%0,%1}, [%2];"
        : "=r"(r[0]), "=r"(r[1]) : "r"(addr));
}
__device__ __forceinline__ void mma16816(float* c, const uint32_t* a, const uint32_t* b) {
    asm volatile("mma.sync.aligned.m16n8k16.row.col.f32.f16.f16.f32 "
        "{%0,%1,%2,%3}, {%4,%5,%6,%7}, {%8,%9}, {%0,%1,%2,%3};"
        : "+f"(c[0]), "+f"(c[1]), "+f"(c[2]), "+f"(c[3])
        : "r"(a[0]), "r"(a[1]), "r"(a[2]), "r"(a[3]), "r"(b[0]), "r"(b[1]));
}

// ---------------------------------------------------------------------------
// Kernel 1: L2-normalize rows of x_i / x_j (fp32 math) into fp16 g_zh.
// ---------------------------------------------------------------------------
__global__ __launch_bounds__(256) void knorm(const float* __restrict__ xi,
                                             const float* __restrict__ xj) {
    int warp = threadIdx.x >> 5;
    int lane = threadIdx.x & 31;
    int row  = blockIdx.x * 8 + warp;
    const float* src = (row < NB) ? (xi + (size_t)row * D)
                                  : (xj + (size_t)(row - NB) * D);
    float4 v0 = ((const float4*)src)[lane];
    float4 v1 = ((const float4*)src)[lane + 32];
    float ss = v0.x*v0.x + v0.y*v0.y + v0.z*v0.z + v0.w*v0.w
             + v1.x*v1.x + v1.y*v1.y + v1.z*v1.z + v1.w*v1.w;
#pragma unroll
    for (int off = 16; off > 0; off >>= 1)
        ss += __shfl_xor_sync(0xffffffffu, ss, off);
    float sc = 1.0f / fmaxf(sqrtf(ss), 1e-12f);
    __half2* dst = (__half2*)(g_zh + (size_t)row * D);
    dst[lane * 2 + 0]  = __floats2half2_rn(v0.x * sc, v0.y * sc);
    dst[lane * 2 + 1]  = __floats2half2_rn(v0.z * sc, v0.w * sc);
    dst[64 + lane * 2] = __floats2half2_rn(v1.x * sc, v1.y * sc);
    dst[65 + lane * 2] = __floats2half2_rn(v1.z * sc, v1.w * sc);
}

// ---------------------------------------------------------------------------
// Stage loader: A(128x32) + B(128x32) fp16 tiles via cp.async.
// ---------------------------------------------------------------------------
__device__ __forceinline__ void load_stage(uint32_t sbase, int rb, int cb,
                                           int k0, int tid) {
    const uint32_t aB = sbase, bB = sbase + BM * PITCH;
#pragma unroll
    for (int i = 0; i < 2; i++) {
        int t = tid + i * 256;
        int row = t >> 2, seg = t & 3;
        uint32_t so = (uint32_t)(row * PITCH + seg * 16);
        cp_async16(aB + so, g_zh + (size_t)(rb + row) * D + k0 + seg * 8);
        cp_async16(bB + so, g_zh + (size_t)(cb + row) * D + k0 + seg * 8);
    }
}

// ---------------------------------------------------------------------------
// Kernel 2: fp16 HMMA sim-GEMM on UPPER-TRIANGULAR tiles only (symmetry).
// Off-diagonal tile (it<jt): exp values feed denom of both rows AND cols.
// Epilogue is 3 sequential passes (exp in-place, row-sum, col-sum) so rsum
// and csum are never simultaneously live -> no spill past the 128-reg cap.
// ---------------------------------------------------------------------------
__global__ __launch_bounds__(256, 2) void kmain_hmma() {
    extern __shared__ char smem[];
    const uint32_t sb = smem_u32(smem);
    float* red_row = (float*)(smem + REDR_OFF);   // [128][4]
    float* red_col = (float*)(smem + REDC_OFF);   // [128][2]

    // Triangular decode: linear blockIdx -> (it, jt), it <= jt.
    int rem = blockIdx.x;
    int it = 0;
    while (rem >= NRT - it) { rem -= NRT - it; it++; }
    const int jt = it + rem;
    const bool offd = (jt > it);
    const bool haspos = (jt == it + NB / BM);   // only these tiles hold gm+NB

    const int tid = threadIdx.x;
    const int wid = tid >> 5, lid = tid & 31;
    const int wm = wid >> 2;                  // 0..1  (rows wm*64)
    const int wn = wid & 3;                   // 0..3  (cols wn*32)
    const int rb = it * BM;
    const int cb = jt * BN;

    float acc[4][4][4];
#pragma unroll
    for (int i = 0; i < 4; i++)
#pragma unroll
        for (int j = 0; j < 4; j++)
#pragma unroll
            for (int e = 0; e < 4; e++) acc[i][j][e] = 0.0f;

    // Prologue: fill 3 of 4 stages
    load_stage(sb + 0 * STAGE_BYTES, rb, cb, 0 * BK, tid); CP_COMMIT();
    load_stage(sb + 1 * STAGE_BYTES, rb, cb, 1 * BK, tid); CP_COMMIT();
    load_stage(sb + 2 * STAGE_BYTES, rb, cb, 2 * BK, tid); CP_COMMIT();

    const int arow  = (lid & 7) + ((lid >> 3) & 1) * 8;
    const int akoff = (lid >> 4) * 16;
    const int brow  = lid & 7;
    const int bkoff = ((lid >> 3) & 1) * 16;

#pragma unroll
    for (int k = 0; k < NKC; k++) {
        if (k <= 5)      { CP_WAIT(2); }
        else if (k == 6) { CP_WAIT(1); }
        else             { CP_WAIT(0); }
        __syncthreads();
        if (k + 3 < NKC) {
            load_stage(sb + ((k + 3) & 3) * STAGE_BYTES, rb, cb, (k + 3) * BK, tid);
            CP_COMMIT();
        }
        const uint32_t aB = sb + (k & 3) * STAGE_BYTES;
        const uint32_t bB = aB + BM * PITCH;
#pragma unroll
        for (int kf = 0; kf < 2; kf++) {
            uint32_t af[4][4], bf[4][2];
#pragma unroll
            for (int i = 0; i < 4; i++)
                ldsm4(af[i], aB + (uint32_t)((wm * 64 + i * 16 + arow) * PITCH
                                             + kf * 32 + akoff));
#pragma unroll
            for (int j = 0; j < 4; j++)
                ldsm2(bf[j], bB + (uint32_t)((wn * 32 + j * 8 + brow) * PITCH
                                             + kf * 32 + bkoff));
#pragma unroll
            for (int i = 0; i < 4; i++)
#pragma unroll
                for (int j = 0; j < 4; j++)
                    mma16816(acc[i][j], af[i], bf[j]);
        }
    }

    // Fragment coords: row = wm*64 + i*16 + (lid>>2) + (e>=2)*8
    //                  col = wn*32 + j*8  + (lid&3)*2 + (e&1)
    const int r0 = lid >> 2;
    const int c0 = (lid & 3) * 2;

    // Pass 0: exp in place (+ pos capture, + self-diagonal mask on diag tiles)
#pragma unroll
    for (int i = 0; i < 4; i++)
#pragma unroll
        for (int j = 0; j < 4; j++)
#pragma unroll
            for (int e = 0; e < 4; e++) {
                const float v = acc[i][j][e];
                float ev = __expf(v * 2.0f);
                if (haspos) {
                    const int lm = wm * 64 + i * 16 + r0 + (e >> 1) * 8;
                    const int ln = wn * 32 + j * 8 + c0 + (e & 1);
                    if (ln == lm) { g_pos[rb + lm] = v; g_pos[cb + ln] = v; }
                }
                if (!offd) {
                    const int lm = wm * 64 + i * 16 + r0 + (e >> 1) * 8;
                    const int ln = wn * 32 + j * 8 + c0 + (e & 1);
                    if (ln == lm) ev = 0.0f;     // exclude self-similarity
                }
                acc[i][j][e] = ev;
            }

    // Pass 1: row sums -> red_row
    {
        float rsum[4][2];
#pragma unroll
        for (int i = 0; i < 4; i++) { rsum[i][0] = 0.0f; rsum[i][1] = 0.0f; }
#pragma unroll
        for (int i = 0; i < 4; i++)
#pragma unroll
            for (int j = 0; j < 4; j++) {
                rsum[i][0] += acc[i][j][0] + acc[i][j][1];
                rsum[i][1] += acc[i][j][2] + acc[i][j][3];
            }
#pragma unroll
        for (int i = 0; i < 4; i++)
#pragma unroll
            for (int h = 0; h < 2; h++) {
#pragma unroll
                for (int off = 1; off <= 2; off <<= 1)
                    rsum[i][h] += __shfl_xor_sync(0xffffffffu, rsum[i][h], off);
            }
        if ((lid & 3) == 0) {
#pragma unroll
            for (int i = 0; i < 4; i++)
#pragma unroll
                for (int h = 0; h < 2; h++)
                    red_row[(wm * 64 + i * 16 + r0 + h * 8) * 4 + wn] = rsum[i][h];
        }
    }

    // Pass 2 (off-diag only): col sums -> red_col
    if (offd) {
        float csum[4][2];
#pragma unroll
        for (int j = 0; j < 4; j++) { csum[j][0] = 0.0f; csum[j][1] = 0.0f; }
#pragma unroll
        for (int i = 0; i < 4; i++)
#pragma unroll
            for (int j = 0; j < 4; j++) {
                csum[j][0] += acc[i][j][0] + acc[i][j][2];
                csum[j][1] += acc[i][j][1] + acc[i][j][3];
            }
#pragma unroll
        for (int j = 0; j < 4; j++)
#pragma unroll
            for (int ec = 0; ec < 2; ec++) {
#pragma unroll
                for (int off = 4; off <= 16; off <<= 1)
                    csum[j][ec] += __shfl_xor_sync(0xffffffffu, csum[j][ec], off);
            }
        if (lid < 4) {
#pragma unroll
            for (int j = 0; j < 4; j++)
#pragma unroll
                for (int ec = 0; ec < 2; ec++)
                    red_col[(wn * 32 + j * 8 + lid * 2 + ec) * 2 + wm] = csum[j][ec];
        }
    }
    __syncthreads();
    if (tid < BM) {
        g_partial[(size_t)(rb + tid) * NCT + jt] =
            red_row[tid * 4] + red_row[tid * 4 + 1]
          + red_row[tid * 4 + 2] + red_row[tid * 4 + 3];
        if (offd)
            g_partial[(size_t)(cb + tid) * NCT + it] =
                red_col[tid * 2] + red_col[tid * 2 + 1];
    }
}

// ---------------------------------------------------------------------------
// Kernel 3: combine partials -> per-row loss -> deterministic scalar reduce.
// ---------------------------------------------------------------------------
__global__ __launch_bounds__(256) void kfinal(float* __restrict__ out) {
    __shared__ float red[256];
    const int tid = threadIdx.x;
    float s = 0.0f;
    for (int r = tid; r < N2; r += 256) {
        float denom = 0.0f;
#pragma unroll
        for (int t = 0; t < NCT; t++) denom += g_partial[(size_t)r * NCT + t];
        s += -g_pos[r] * 2.0f + logf(denom);
    }
    red[tid] = s;
    __syncthreads();
    for (int off = 128; off > 0; off >>= 1) {
        if (tid < off) red[tid] += red[tid + off];
        __syncthreads();
    }
    if (tid == 0) out[0] = red[0] / (float)N2;
}

// ---------------------------------------------------------------------------
extern "C" void kernel_launch(void* const* d_in, const int* in_sizes, int n_in,
                              void* d_out, int out_size) {
    const float* xi = (const float*)d_in[0];
    const float* xj = (const float*)d_in[1];
    float* out = (float*)d_out;
    (void)in_sizes; (void)n_in; (void)out_size;

    cudaFuncSetAttribute(kmain_hmma,
                         cudaFuncAttributeMaxDynamicSharedMemorySize, SMEM_BYTES);

    knorm<<<N2 / 8, 256>>>(xi, xj);
    kmain_hmma<<<NTRI, 256, SMEM_BYTES>>>();
    kfinal<<<1, 256>>>(out);
}

// round 6
// speedup vs baseline: 13.3490x; 4.5849x over previous
#include <cuda_runtime.h>
#include <cuda_fp16.h>
#include <math.h>
#include <stdint.h>

// Problem constants (fixed shapes: B=4096, D=256, T=0.5)
#define NB     4096
#define D      256
#define N2     8192
#define BM     128
#define BN     128
#define BK     32
#define NKC    (D / BK)      // 8 k-chunks
#define NCT    (N2 / BN)     // 64 col tiles
#define NRT    (N2 / BM)     // 64 row tiles
#define NTRI   (NRT * (NRT + 1) / 2)   // 2080 upper-tri tiles
#define PITCH  80            // smem row pitch bytes (64B data + 16B pad)
#define STAGE_BYTES (2 * BM * PITCH)   // A + B tile = 20480
#define NSTAGE 4
#define REDR_OFF (NSTAGE * STAGE_BYTES)          // 81920: red_row[128][4]
#define REDC_OFF (REDR_OFF + BM * 4 * 4)         // red_col[128][2]
#define SMEM_BYTES (REDC_OFF + BM * 2 * 4)
#define FBLK   64            // kfinal1 blocks (128 rows each)

// Scratch (static device globals; no allocation allowed)
__device__ __half g_zh[N2 * D];        // normalized rows, fp16
__device__ float g_partial[N2 * NCT];  // per-row exp-sum partial per slot
__device__ float g_pos[N2];            // sim[k, k +- NB]
__device__ float g_blocksum[FBLK];     // per-block loss partial

// ---------------------------------------------------------------------------
__device__ __forceinline__ uint32_t smem_u32(const void* p) {
    uint32_t a;
    asm("{ .reg .u64 t; cvta.to.shared.u64 t, %1; cvt.u32.u64 %0, t; }"
        : "=r"(a) : "l"(p));
    return a;
}
__device__ __forceinline__ void cp_async16(uint32_t smem, const void* g) {
    asm volatile("cp.async.cg.shared.global [%0], [%1], 16;" :: "r"(smem), "l"(g));
}
#define CP_COMMIT() asm volatile("cp.async.commit_group;" ::: "memory")
#define CP_WAIT(n)  asm volatile("cp.async.wait_group %0;" :: "n"(n) : "memory")

__device__ __forceinline__ void ldsm4(uint32_t* r, uint32_t addr) {
    asm volatile("ldmatrix.sync.aligned.m8n8.x4.shared.b16 {%0,%1,%2,%3}, [%4];"
        : "=r"(r[0]), "=r"(r[1]), "=r"(r[2]), "=r"(r[3]) : "r"(addr));
}
__device__ __forceinline__ void ldsm2(uint32_t* r, uint32_t addr) {
    asm volatile("ldmatrix.sync.aligned.m8n8.x2.shared.b16 {%0,%1}, [%2];"
        : "=r"(r[0]), "=r"(r[1]) : "r"(addr));
}
__device__ __forceinline__ void mma16816(float* c, const uint32_t* a, const uint32_t* b) {
    asm volatile("mma.sync.aligned.m16n8k16.row.col.f32.f16.f16.f32 "
        "{%0,%1,%2,%3}, {%4,%5,%6,%7}, {%8,%9}, {%0,%1,%2,%3};"
        : "+f"(c[0]), "+f"(c[1]), "+f"(c[2]), "+f"(c[3])
        : "r"(a[0]), "r"(a[1]), "r"(a[2]), "r"(a[3]), "r"(b[0]), "r"(b[1]));
}

// ---------------------------------------------------------------------------
// Kernel 1: L2-normalize rows of x_i / x_j (fp32 math) into fp16 g_zh.
// ---------------------------------------------------------------------------
__global__ __launch_bounds__(256) void knorm(const float* __restrict__ xi,
                                             const float* __restrict__ xj) {
    int warp = threadIdx.x >> 5;
    int lane = threadIdx.x & 31;
    int row  = blockIdx.x * 8 + warp;
    const float* src = (row < NB) ? (xi + (size_t)row * D)
                                  : (xj + (size_t)(row - NB) * D);
    float4 v0 = ((const float4*)src)[lane];
    float4 v1 = ((const float4*)src)[lane + 32];
    float ss = v0.x*v0.x + v0.y*v0.y + v0.z*v0.z + v0.w*v0.w
             + v1.x*v1.x + v1.y*v1.y + v1.z*v1.z + v1.w*v1.w;
#pragma unroll
    for (int off = 16; off > 0; off >>= 1)
        ss += __shfl_xor_sync(0xffffffffu, ss, off);
    float sc = 1.0f / fmaxf(sqrtf(ss), 1e-12f);
    __half2* dst = (__half2*)(g_zh + (size_t)row * D);
    dst[lane * 2 + 0]  = __floats2half2_rn(v0.x * sc, v0.y * sc);
    dst[lane * 2 + 1]  = __floats2half2_rn(v0.z * sc, v0.w * sc);
    dst[64 + lane * 2] = __floats2half2_rn(v1.x * sc, v1.y * sc);
    dst[65 + lane * 2] = __floats2half2_rn(v1.z * sc, v1.w * sc);
}

// ---------------------------------------------------------------------------
// Stage loader: A(128x32) + B(128x32) fp16 tiles via cp.async.
// ---------------------------------------------------------------------------
__device__ __forceinline__ void load_stage(uint32_t sbase, int rb, int cb,
                                           int k0, int tid) {
    const uint32_t aB = sbase, bB = sbase + BM * PITCH;
#pragma unroll
    for (int i = 0; i < 2; i++) {
        int t = tid + i * 256;
        int row = t >> 2, seg = t & 3;
        uint32_t so = (uint32_t)(row * PITCH + seg * 16);
        cp_async16(aB + so, g_zh + (size_t)(rb + row) * D + k0 + seg * 8);
        cp_async16(bB + so, g_zh + (size_t)(cb + row) * D + k0 + seg * 8);
    }
}

// ---------------------------------------------------------------------------
// Kernel 2: fp16 HMMA sim-GEMM on UPPER-TRIANGULAR tiles only (symmetry).
// Off-diagonal tile (it<jt): exp values feed denom of both rows AND cols.
// ---------------------------------------------------------------------------
__global__ __launch_bounds__(256, 2) void kmain_hmma() {
    extern __shared__ char smem[];
    const uint32_t sb = smem_u32(smem);
    float* red_row = (float*)(smem + REDR_OFF);   // [128][4]
    float* red_col = (float*)(smem + REDC_OFF);   // [128][2]

    // Triangular decode: linear blockIdx -> (it, jt), it <= jt.
    int rem = blockIdx.x;
    int it = 0;
    while (rem >= NRT - it) { rem -= NRT - it; it++; }
    const int jt = it + rem;
    const bool offd = (jt > it);
    const bool haspos = (jt == it + NB / BM);   // only these tiles hold gm+NB

    const int tid = threadIdx.x;
    const int wid = tid >> 5, lid = tid & 31;
    const int wm = wid >> 2;                  // 0..1  (rows wm*64)
    const int wn = wid & 3;                   // 0..3  (cols wn*32)
    const int rb = it * BM;
    const int cb = jt * BN;

    float acc[4][4][4];
#pragma unroll
    for (int i = 0; i < 4; i++)
#pragma unroll
        for (int j = 0; j < 4; j++)
#pragma unroll
            for (int e = 0; e < 4; e++) acc[i][j][e] = 0.0f;

    // Prologue: fill 3 of 4 stages
    load_stage(sb + 0 * STAGE_BYTES, rb, cb, 0 * BK, tid); CP_COMMIT();
    load_stage(sb + 1 * STAGE_BYTES, rb, cb, 1 * BK, tid); CP_COMMIT();
    load_stage(sb + 2 * STAGE_BYTES, rb, cb, 2 * BK, tid); CP_COMMIT();

    const int arow  = (lid & 7) + ((lid >> 3) & 1) * 8;
    const int akoff = (lid >> 4) * 16;
    const int brow  = lid & 7;
    const int bkoff = ((lid >> 3) & 1) * 16;

#pragma unroll
    for (int k = 0; k < NKC; k++) {
        if (k <= 5)      { CP_WAIT(2); }
        else if (k == 6) { CP_WAIT(1); }
        else             { CP_WAIT(0); }
        __syncthreads();
        if (k + 3 < NKC) {
            load_stage(sb + ((k + 3) & 3) * STAGE_BYTES, rb, cb, (k + 3) * BK, tid);
            CP_COMMIT();
        }
        const uint32_t aB = sb + (k & 3) * STAGE_BYTES;
        const uint32_t bB = aB + BM * PITCH;
#pragma unroll
        for (int kf = 0; kf < 2; kf++) {
            uint32_t af[4][4], bf[4][2];
#pragma unroll
            for (int i = 0; i < 4; i++)
                ldsm4(af[i], aB + (uint32_t)((wm * 64 + i * 16 + arow) * PITCH
                                             + kf * 32 + akoff));
#pragma unroll
            for (int j = 0; j < 4; j++)
                ldsm2(bf[j], bB + (uint32_t)((wn * 32 + j * 8 + brow) * PITCH
                                             + kf * 32 + bkoff));
#pragma unroll
            for (int i = 0; i < 4; i++)
#pragma unroll
                for (int j = 0; j < 4; j++)
                    mma16816(acc[i][j], af[i], bf[j]);
        }
    }

    // Fragment coords: row = wm*64 + i*16 + (lid>>2) + (e>=2)*8
    //                  col = wn*32 + j*8  + (lid&3)*2 + (e&1)
    const int r0 = lid >> 2;
    const int c0 = (lid & 3) * 2;

    // Pass 0: exp in place (+ pos capture, + self-diagonal mask on diag tiles)
#pragma unroll
    for (int i = 0; i < 4; i++)
#pragma unroll
        for (int j = 0; j < 4; j++)
#pragma unroll
            for (int e = 0; e < 4; e++) {
                const float v = acc[i][j][e];
                float ev = __expf(v * 2.0f);
                if (haspos) {
                    const int lm = wm * 64 + i * 16 + r0 + (e >> 1) * 8;
                    const int ln = wn * 32 + j * 8 + c0 + (e & 1);
                    if (ln == lm) { g_pos[rb + lm] = v; g_pos[cb + ln] = v; }
                }
                if (!offd) {
                    const int lm = wm * 64 + i * 16 + r0 + (e >> 1) * 8;
                    const int ln = wn * 32 + j * 8 + c0 + (e & 1);
                    if (ln == lm) ev = 0.0f;     // exclude self-similarity
                }
                acc[i][j][e] = ev;
            }

    // Pass 1: row sums -> red_row
    {
        float rsum[4][2];
#pragma unroll
        for (int i = 0; i < 4; i++) { rsum[i][0] = 0.0f; rsum[i][1] = 0.0f; }
#pragma unroll
        for (int i = 0; i < 4; i++)
#pragma unroll
            for (int j = 0; j < 4; j++) {
                rsum[i][0] += acc[i][j][0] + acc[i][j][1];
                rsum[i][1] += acc[i][j][2] + acc[i][j][3];
            }
#pragma unroll
        for (int i = 0; i < 4; i++)
#pragma unroll
            for (int h = 0; h < 2; h++) {
#pragma unroll
                for (int off = 1; off <= 2; off <<= 1)
                    rsum[i][h] += __shfl_xor_sync(0xffffffffu, rsum[i][h], off);
            }
        if ((lid & 3) == 0) {
#pragma unroll
            for (int i = 0; i < 4; i++)
#pragma unroll
                for (int h = 0; h < 2; h++)
                    red_row[(wm * 64 + i * 16 + r0 + h * 8) * 4 + wn] = rsum[i][h];
        }
    }

    // Pass 2 (off-diag only): col sums -> red_col
    if (offd) {
        float csum[4][2];
#pragma unroll
        for (int j = 0; j < 4; j++) { csum[j][0] = 0.0f; csum[j][1] = 0.0f; }
#pragma unroll
        for (int i = 0; i < 4; i++)
#pragma unroll
            for (int j = 0; j < 4; j++) {
                csum[j][0] += acc[i][j][0] + acc[i][j][2];
                csum[j][1] += acc[i][j][1] + acc[i][j][3];
            }
#pragma unroll
        for (int j = 0; j < 4; j++)
#pragma unroll
            for (int ec = 0; ec < 2; ec++) {
#pragma unroll
                for (int off = 4; off <= 16; off <<= 1)
                    csum[j][ec] += __shfl_xor_sync(0xffffffffu, csum[j][ec], off);
            }
        if (lid < 4) {
#pragma unroll
            for (int j = 0; j < 4; j++)
#pragma unroll
                for (int ec = 0; ec < 2; ec++)
                    red_col[(wn * 32 + j * 8 + lid * 2 + ec) * 2 + wm] = csum[j][ec];
        }
    }
    __syncthreads();
    if (tid < BM) {
        g_partial[(size_t)(rb + tid) * NCT + jt] =
            red_row[tid * 4] + red_row[tid * 4 + 1]
          + red_row[tid * 4 + 2] + red_row[tid * 4 + 3];
        if (offd)
            g_partial[(size_t)(cb + tid) * NCT + it] =
                red_col[tid * 2] + red_col[tid * 2 + 1];
    }
}

// ---------------------------------------------------------------------------
// Kernel 3a: parallel, coalesced per-row loss. One warp handles rows of its
// group; lanes read g_partial[row*64 + lane(+32)] -> 2 coalesced lines.
// 64 blocks x 256 threads; block b covers rows [b*128, b*128+128).
// ---------------------------------------------------------------------------
__global__ __launch_bounds__(256) void kfinal1() {
    __shared__ float red[8];
    const int warp = threadIdx.x >> 5;
    const int lane = threadIdx.x & 31;
    float acc = 0.0f;
#pragma unroll
    for (int rr = 0; rr < 16; rr++) {
        const int row = blockIdx.x * 128 + warp * 16 + rr;
        const float* p = g_partial + (size_t)row * NCT;
        float s = p[lane] + p[lane + 32];
#pragma unroll
        for (int off = 16; off > 0; off >>= 1)
            s += __shfl_xor_sync(0xffffffffu, s, off);
        if (lane == 0) acc += -g_pos[row] * 2.0f + logf(s);
    }
    if (lane == 0) red[warp] = acc;
    __syncthreads();
    if (threadIdx.x == 0) {
        float t = 0.0f;
#pragma unroll
        for (int w = 0; w < 8; w++) t += red[w];
        g_blocksum[blockIdx.x] = t;
    }
}

// Kernel 3b: deterministic final combine.
__global__ void kfinal2(float* __restrict__ out) {
    if (threadIdx.x == 0) {
        float t = 0.0f;
#pragma unroll
        for (int b = 0; b < FBLK; b++) t += g_blocksum[b];
        out[0] = t / (float)N2;
    }
}

// ---------------------------------------------------------------------------
extern "C" void kernel_launch(void* const* d_in, const int* in_sizes, int n_in,
                              void* d_out, int out_size) {
    const float* xi = (const float*)d_in[0];
    const float* xj = (const float*)d_in[1];
    float* out = (float*)d_out;
    (void)in_sizes; (void)n_in; (void)out_size;

    cudaFuncSetAttribute(kmain_hmma,
                         cudaFuncAttributeMaxDynamicSharedMemorySize, SMEM_BYTES);

    knorm<<<N2 / 8, 256>>>(xi, xj);
    kmain_hmma<<<NTRI, 256, SMEM_BYTES>>>();
    kfinal1<<<FBLK, 256>>>();
    kfinal2<<<1, 32>>>(out);
}